// round 14
// baseline (speedup 1.0000x reference)
#include <cuda_runtime.h>
#include <cstdint>

// FlowNetC correlation cost volume. Inputs [B=8, C=128, H=128, W=256] fp32.
// out[b, (dy+4)*9+(dx+4), y, x] = (1/128) * sum_c in1[b,c,y,x] * in2z[b,c,y+dy,x+dx]
//
// R11: dy-inside-block + aligned-odd packing.
// Block = 9 warps (288 thr) <-> (y, xhalf, b); warp w handles dy = w-4 for the
// whole 128-col half. All 9 warps LDG the SAME in1 row -> 1 L2 miss + 8 L1
// hits (a-traffic /9). Each warp cp.async-stages its dy-shifted in2 row window
// (136 floats, 4-col zero halos) into warp-private double-buffered smem
// (CHUNK=8 channels/phase); no block barriers.
// Math per thread (4 cols, window bb[0..11] <-> cols x-4..x+7):
//   even d=2e:  acc2 pairs (c0,c1),(c2,c3) += (a0,a1)|(a2,a3) * bp[e]|bp[e+1]
//   odd  d=2e+1: pair (c1,c2) += (a1,a2)*bp[e+1]  (ALIGNED b-pair);
//                cols 0,3 scalar FFMA. (a1,a2) packed once, reused for all e.

#define B_     8
#define C_     128
#define H_     128
#define W_     256
#define CHUNK  8                     // channels per staged phase
#define ROWF   136                   // floats per row window (4-col halo each side)
#define PHASEF (CHUNK * ROWF)        // 1088 floats
#define WARPBUF (2 * PHASEF)         // 2176 floats (double buffer)
#define NWARP  9
#define SMEM_BYTES (NWARP * WARPBUF * 4)   // 78,336 B per CTA -> 2 CTAs/SM

__device__ __forceinline__ void cp_async16(void* dst_smem, const void* src_gmem) {
    uint32_t d = (uint32_t)__cvta_generic_to_shared(dst_smem);
    asm volatile("cp.async.cg.shared.global [%0], [%1], 16;"
                 :: "r"(d), "l"(src_gmem) : "memory");
}
__device__ __forceinline__ void cp_commit() {
    asm volatile("cp.async.commit_group;" ::: "memory");
}
template <int N>
__device__ __forceinline__ void cp_wait() {
    asm volatile("cp.async.wait_group %0;" :: "n"(N) : "memory");
}
__device__ __forceinline__ unsigned long long pk2(float lo, float hi) {
    unsigned long long r;
    asm("mov.b64 %0, {%1, %2};" : "=l"(r) : "f"(lo), "f"(hi));
    return r;
}
__device__ __forceinline__ void fma2(unsigned long long& d,
                                     unsigned long long a, unsigned long long b) {
    asm("fma.rn.f32x2 %0, %1, %2, %0;" : "+l"(d) : "l"(a), "l"(b));
}
__device__ __forceinline__ float2 up2(unsigned long long v) {
    float2 r;
    asm("mov.b64 {%0, %1}, %2;" : "=f"(r.x), "=f"(r.y) : "l"(v));
    return r;
}

extern __shared__ float s_mem[];

__global__ __launch_bounds__(32 * NWARP, 2)
void corr_kernel(const float* __restrict__ in1,
                 const float* __restrict__ in2,
                 float* __restrict__ out)
{
    const int y     = (int)blockIdx.x;            // output row
    const int xh    = (int)blockIdx.y;            // 128-col half
    const int b     = (int)blockIdx.z;
    const int xbase = xh << 7;
    const int w     = (int)threadIdx.x >> 5;      // warp id -> dy = w-4
    const int lane  = (int)threadIdx.x & 31;
    const int dy    = w - 4;
    const int gy    = y + dy;
    const bool rowok = (unsigned)gy < (unsigned)H_;

    const float* in1b = in1 + (size_t)b * C_ * H_ * W_;
    const float* in2g = in2 + (size_t)b * C_ * H_ * W_ + (size_t)(rowok ? gy : 0) * W_;

    float* wbuf = s_mem + w * WARPBUF;

    // Zero warp-private buffer once: halos / OOB rows stay zero.
    for (int i = lane; i < WARPBUF; i += 32) wbuf[i] = 0.0f;
    __syncwarp();

    // Accumulators: even d -> 2 f32x2 per d (cols 01, 23); odd d -> 1 f32x2
    // (cols 12) + 2 scalars (cols 0, 3). 36 fp32 total.
    unsigned long long ae[5][2], aom[4];
    float ao0[4], ao3[4];
#pragma unroll
    for (int e = 0; e < 5; ++e) { ae[e][0] = 0ull; ae[e][1] = 0ull; }
#pragma unroll
    for (int e = 0; e < 4; ++e) { aom[e] = 0ull; ao0[e] = 0.0f; ao3[e] = 0.0f; }

    // Stage CHUNK channels of this warp's in2 row window into phase ph.
    // float4 slot s <-> global f4 index g0+s, valid iff 0 <= g0+s < 64.
    const int g0 = (xh << 5) - 1;
    auto stage = [&](int c0, int ph) {
        if (!rowok) return;
        float* pb = wbuf + ph * PHASEF;
#pragma unroll
        for (int c = 0; c < CHUNK; ++c) {
            const float* src = in2g + (size_t)(c0 + c) * H_ * W_;
            float* drow = pb + c * ROWF;
            int gf4 = g0 + lane;                  // slots 0..31
            if ((unsigned)gf4 < 64u)
                cp_async16(drow + (lane << 2), src + (gf4 << 2));
            if (lane < 2) {                       // slots 32..33
                int gf4b = g0 + 32 + lane;
                if ((unsigned)gf4b < 64u)
                    cp_async16(drow + ((32 + lane) << 2), src + (gf4b << 2));
            }
        }
    };

    stage(0, 0);
    cp_commit();

    const int NCHUNK = C_ / CHUNK;   // 16
#pragma unroll 2
    for (int k = 0; k < NCHUNK; ++k) {
        if (k < NCHUNK - 1) {
            stage((k + 1) * CHUNK, (k + 1) & 1);
            cp_commit();
            cp_wait<1>();            // chunk k's group complete
        } else {
            cp_wait<0>();
        }
        __syncwarp();

        const float* pb   = wbuf + (k & 1) * PHASEF;
        // All 9 warps read the SAME a row -> L1 serves 8 of 9.
        const float* aptr = in1b + ((size_t)(k * CHUNK) * H_ + y) * W_
                                 + xbase + (lane << 2);

#pragma unroll
        for (int c = 0; c < CHUNK; ++c) {
            float4 a = *reinterpret_cast<const float4*>(aptr + (size_t)c * H_ * W_);
            const float* br = pb + c * ROWF + (lane << 2);   // bb[j] <-> col x-4+j
            float4 b0 = *reinterpret_cast<const float4*>(br);
            float4 b1 = *reinterpret_cast<const float4*>(br + 4);
            float4 b2 = *reinterpret_cast<const float4*>(br + 8);
            float bb[12] = {b0.x, b0.y, b0.z, b0.w,
                            b1.x, b1.y, b1.z, b1.w,
                            b2.x, b2.y, b2.z, b2.w};

            unsigned long long bp[6];             // aligned halves of LDS.128: free
#pragma unroll
            for (int i = 0; i < 6; ++i) bp[i] = pk2(bb[2 * i], bb[2 * i + 1]);
            unsigned long long a01 = pk2(a.x, a.y);   // aligned
            unsigned long long a23 = pk2(a.z, a.w);   // aligned
            unsigned long long a12 = pk2(a.y, a.z);   // ONE unaligned pack, reused 4x

            // even d = 2e
#pragma unroll
            for (int e = 0; e < 5; ++e) {
                fma2(ae[e][0], a01, bp[e]);
                fma2(ae[e][1], a23, bp[e + 1]);
            }
            // odd d = 2e+1: pair (cols 1,2) uses ALIGNED bp[e+1]; cols 0,3 scalar
#pragma unroll
            for (int e = 0; e < 4; ++e) {
                fma2(aom[e], a12, bp[e + 1]);                   // b idx 2e+2, 2e+3
                ao0[e] = fmaf(a.x, bb[2 * e + 1], ao0[e]);      // col 0: b idx d
                ao3[e] = fmaf(a.w, bb[2 * e + 4], ao3[e]);      // col 3: b idx d+3
            }
        }
        // no barrier: LDS of chunk k done ~29cyc after issue; earliest
        // overwrite (chunk k+2's cp.async) lands >=234cyc after its issue.
    }

    // ---- epilogue: scale by 1/C, one float4 store per dx ----
    const float sc = 1.0f / (float)C_;
    const size_t ob = (((size_t)b * 81 + (size_t)(dy + 4) * 9) * H_ + y) * W_
                    + xbase + (lane << 2);
#pragma unroll
    for (int e = 0; e < 5; ++e) {                 // d = 2e
        float2 lo = up2(ae[e][0]), hi = up2(ae[e][1]);
        float4 v = make_float4(lo.x * sc, lo.y * sc, hi.x * sc, hi.y * sc);
        *reinterpret_cast<float4*>(out + ob + (size_t)(2 * e) * H_ * W_) = v;
    }
#pragma unroll
    for (int e = 0; e < 4; ++e) {                 // d = 2e+1
        float2 m = up2(aom[e]);
        float4 v = make_float4(ao0[e] * sc, m.x * sc, m.y * sc, ao3[e] * sc);
        *reinterpret_cast<float4*>(out + ob + (size_t)(2 * e + 1) * H_ * W_) = v;
    }
}

extern "C" void kernel_launch(void* const* d_in, const int* in_sizes, int n_in,
                              void* d_out, int out_size)
{
    const float* in1 = (const float*)d_in[0];
    const float* in2 = (const float*)d_in[1];
    float* out = (float*)d_out;

    cudaFuncSetAttribute(corr_kernel,
                         cudaFuncAttributeMaxDynamicSharedMemorySize, SMEM_BYTES);

    // (y, xhalf, b): dy lives INSIDE the block (9 warps share one a row).
    dim3 grid(H_, 2, B_);
    corr_kernel<<<grid, 32 * NWARP, SMEM_BYTES>>>(in1, in2, out);
}